// round 16
// baseline (speedup 1.0000x reference)
#include <cuda_runtime.h>
#include <cuda_fp16.h>
#include <math.h>
#include <stdint.h>

#define N_TOK 8192
#define D_DIM 1024
#define E_NUM 8
#define H_DIM 4096
#define CAP   8192
#define PAIRS 16384

#define TK 32            // fp16 elems per k-chunk (64 bytes per row)
#define ROWB 80          // padded SMEM row bytes (64 data + 16 pad)

// ---------------- device scratch ----------------
__device__ int   g_cnt[E_NUM];
__device__ int   g_off[E_NUM];
__device__ int   g_tok[E_NUM * CAP];
__device__ float g_wt [E_NUM * CAP];

__device__ __half g_xh[(size_t)N_TOK * D_DIM];
__device__ __half g_hh[(size_t)PAIRS * H_DIM];
__device__ __half g_B1h[(size_t)E_NUM * H_DIM * D_DIM];
__device__ __half g_B2h[(size_t)E_NUM * D_DIM * H_DIM];

// ---------------- helpers ----------------
__device__ __forceinline__ uint32_t smem_u32(const void* p) {
    return (uint32_t)__cvta_generic_to_shared(p);
}
#define CP16(dst, src) \
    asm volatile("cp.async.cg.shared.global [%0], [%1], 16;" :: "r"(dst), "l"(src) : "memory")
#define CP_COMMIT() asm volatile("cp.async.commit_group;" ::: "memory")

__device__ __forceinline__ void ldsm4(uint32_t* r, uint32_t addr) {
    asm volatile("ldmatrix.sync.aligned.m8n8.x4.shared.b16 {%0,%1,%2,%3}, [%4];"
        : "=r"(r[0]), "=r"(r[1]), "=r"(r[2]), "=r"(r[3]) : "r"(addr));
}
__device__ __forceinline__ void mma_f16(float* c, const uint32_t* a, const uint32_t* b) {
    asm volatile("mma.sync.aligned.m16n8k16.row.col.f32.f16.f16.f32 "
        "{%0,%1,%2,%3}, {%4,%5,%6,%7}, {%8,%9}, {%0,%1,%2,%3};"
        : "+f"(c[0]), "+f"(c[1]), "+f"(c[2]), "+f"(c[3])
        : "r"(a[0]), "r"(a[1]), "r"(a[2]), "r"(a[3]), "r"(b[0]), "r"(b[1]));
}
// vector reduction add (sm_90+): one 8B RMW, two fp32 adds
__device__ __forceinline__ void red_add_v2(float* addr, float v0, float v1) {
    asm volatile("red.global.add.v2.f32 [%0], {%1, %2};"
        :: "l"(addr), "f"(v0), "f"(v1) : "memory");
}

// ---------------- small kernels ----------------
__global__ void zero_kernel(float* __restrict__ out, int n) {
    int i = blockIdx.x * blockDim.x + threadIdx.x;
    if (i < E_NUM) g_cnt[i] = 0;
    for (; i < n; i += gridDim.x * blockDim.x) out[i] = 0.0f;
}

// W[e][K][N] fp32 -> P[e][N][K] fp16 hi (32x32 tile transpose)
__global__ __launch_bounds__(256)
void pack_w_kernel(const float* __restrict__ W, __half* __restrict__ Ph, int K, int N) {
    __shared__ float s[32][33];
    const int k0 = blockIdx.x * 32, n0 = blockIdx.y * 32, e = blockIdx.z;
    const int tid = threadIdx.x;
    const int kk = tid >> 5, nn = tid & 31;
#pragma unroll
    for (int i = 0; i < 4; i++)
        s[kk + i * 8][nn] = W[((size_t)e * K + k0 + kk + i * 8) * N + n0 + nn];
    __syncthreads();
    const int n_r = tid >> 4;
    const int kp  = (tid & 15) * 2;
#pragma unroll
    for (int i = 0; i < 2; i++) {
        int nr = n_r + i * 16;
        __half2 hp;
        hp.x = __float2half_rn(s[kp][nr]);
        hp.y = __float2half_rn(s[kp + 1][nr]);
        size_t o = ((size_t)e * N + n0 + nr) * K + k0 + kp;
        *(__half2*)(Ph + o) = hp;
    }
}

// router + x->fp16 conversion fused (one warp per token)
__global__ void router_kernel(const float* __restrict__ x,
                              const float* __restrict__ Wr,
                              const float* __restrict__ br) {
    int warp = (blockIdx.x * blockDim.x + threadIdx.x) >> 5;
    int lane = threadIdx.x & 31;
    if (warp >= N_TOK) return;
    const float* xr = x + (size_t)warp * D_DIM;
    __half* xo = g_xh + (size_t)warp * D_DIM;
    float acc[8];
#pragma unroll
    for (int e = 0; e < 8; e++) acc[e] = 0.0f;
    for (int d = lane; d < D_DIM; d += 32) {
        float xv = xr[d];
        xo[d] = __float2half_rn(xv);
        const float4* w4 = (const float4*)(Wr + (size_t)d * E_NUM);
        float4 a = w4[0], b = w4[1];
        acc[0] += xv * a.x; acc[1] += xv * a.y; acc[2] += xv * a.z; acc[3] += xv * a.w;
        acc[4] += xv * b.x; acc[5] += xv * b.y; acc[6] += xv * b.z; acc[7] += xv * b.w;
    }
#pragma unroll
    for (int off = 16; off > 0; off >>= 1)
#pragma unroll
        for (int e = 0; e < 8; e++)
            acc[e] += __shfl_down_sync(0xffffffffu, acc[e], off);
    if (lane == 0) {
        float lg[8];
#pragma unroll
        for (int e = 0; e < 8; e++) lg[e] = acc[e] + br[e];
        int e0 = 0;
#pragma unroll
        for (int e = 1; e < 8; e++) if (lg[e] > lg[e0]) e0 = e;
        int e1 = (e0 == 0) ? 1 : 0;
#pragma unroll
        for (int e = 0; e < 8; e++)
            if (e != e0 && e != e1 && lg[e] > lg[e1]) e1 = e;
        float z  = __expf(lg[e1] - lg[e0]);
        float w0 = 1.0f / (1.0f + z);
        float w1 = z * w0;
        int p0 = atomicAdd(&g_cnt[e0], 1);
        g_tok[e0 * CAP + p0] = warp;  g_wt[e0 * CAP + p0] = w0;
        int p1 = atomicAdd(&g_cnt[e1], 1);
        g_tok[e1 * CAP + p1] = warp;  g_wt[e1 * CAP + p1] = w1;
    }
}

__global__ void offsets_kernel() {
    if (threadIdx.x == 0 && blockIdx.x == 0) {
        int acc = 0;
#pragma unroll
        for (int e = 0; e < E_NUM; e++) { g_off[e] = acc; acc += g_cnt[e]; }
    }
}

// ---- grouped GEMM: mma.sync fp16 single-term, 128 x 256 tile, 512 threads ----
// PHASE 1 (NST=4): -> relu -> g_hh fp16
// PHASE 2 (NST=4): -> weighted red.v2 scatter into out
template <int PHASE, int KDIM, int NDIM, int NST>
__global__ __launch_bounds__(512, 1)
void moe_hmma(const __half* __restrict__ Ahg,
              const __half* __restrict__ Bhg,
              const float* __restrict__ bias,
              float* __restrict__ out) {
    constexpr int C   = KDIM / TK;
    constexpr int TMV = 128;
    constexpr int MT  = 2;             // warp M tile 32
    constexpr int AHo = 0;
    constexpr int BHo = TMV * ROWB;
    constexpr uint32_t STGv = (uint32_t)(TMV + 256) * ROWB;   // 30720

    const int e  = blockIdx.z;
    const int Ne = g_cnt[e];
    const int m0 = blockIdx.x * TMV;
    if (m0 >= Ne) return;
    const int n0 = blockIdx.y * 256;
    const int base = g_off[e];

    extern __shared__ __align__(128) char smem[];
    const uint32_t sb = smem_u32(smem);
    const int tid = threadIdx.x;

    // ---- A loads: 128 rows, thread -> row (tid>>2), 16B seg (tid&3) ----
    const int ar = tid >> 2;            // 0..127
    const int asg = (tid & 3) * 16;
    const char* ahp;
    {
        int rr = min(m0 + ar, Ne - 1);
        size_t i0 = (PHASE == 1) ? (size_t)g_tok[e * CAP + rr] : (size_t)(base + rr);
        ahp = (const char*)(Ahg + i0 * KDIM) + asg;
    }
    const uint32_t dA = (uint32_t)ar * ROWB + asg;

    // ---- B loads: 256 rows, thread -> row (tid>>1), 2 x 16B segs ----
    const int brr = tid >> 1;           // 0..255
    const int bsg = (tid & 1) * 32;
    const char* bh0 = (const char*)(Bhg + ((size_t)e * NDIM + n0 + brr) * KDIM) + bsg;
    const uint32_t dB = (uint32_t)brr * ROWB + bsg;

    auto issue = [&](int c) {
        if (c < C) {
            uint32_t st = sb + (uint32_t)(c % NST) * STGv;
            int cb = c * 64;   // bytes per chunk along K
            CP16(st + AHo + dA, ahp + cb);
            CP16(st + BHo + dB,      bh0 + cb);
            CP16(st + BHo + dB + 16, bh0 + cb + 16);
        }
        CP_COMMIT();
    };

    float acc[MT][8][4];
#pragma unroll
    for (int i = 0; i < MT; i++)
#pragma unroll
        for (int j = 0; j < 8; j++)
#pragma unroll
            for (int k = 0; k < 4; k++) acc[i][j][k] = 0.0f;

    const int lane = tid & 31, wid = tid >> 5;
    const int wm = (wid & 3) * 32;        // warp M offset (4 slots x 32 = 128)
    const int wn = (wid >> 2) * 64;       // warp N offset (4 slots x 64 = 256)
    const uint32_t a_off = (uint32_t)(wm + (lane & 15)) * ROWB + (lane >> 4) * 16;
    const uint32_t b_off = (uint32_t)(wn + (lane & 7) + ((lane >> 4) & 1) * 8) * ROWB
                         + ((lane >> 3) & 1) * 16;

#pragma unroll
    for (int p = 0; p < NST - 1; p++) issue(p);

    for (int c = 0; c < C; c++) {
        asm volatile("cp.async.wait_group %0;" :: "n"(NST - 2) : "memory");
        __syncthreads();
        issue(c + NST - 1);

        const uint32_t st = sb + (uint32_t)(c % NST) * STGv;
#pragma unroll
        for (int kk = 0; kk < 2; kk++) {
            uint32_t af[4 * MT], tf[16];
#pragma unroll
            for (int tn2 = 0; tn2 < 4; tn2++)
                ldsm4(tf + tn2 * 4, st + BHo + b_off + tn2 * 16 * ROWB + kk * 32);
#pragma unroll
            for (int tm = 0; tm < MT; tm++)
                ldsm4(af + tm * 4, st + AHo + a_off + tm * 16 * ROWB + kk * 32);
#pragma unroll
            for (int tm = 0; tm < MT; tm++)
#pragma unroll
                for (int tn = 0; tn < 8; tn++)
                    mma_f16(acc[tm][tn], af + tm * 4, tf + tn * 2);
        }
    }

    // ---- epilogue ----
    const int lr_base  = wm + (lane >> 2);
    const int col_base = n0 + wn + 2 * (lane & 3);
    const float* bp = bias + (size_t)e * NDIM;
#pragma unroll
    for (int tm = 0; tm < MT; tm++) {
#pragma unroll
        for (int half = 0; half < 2; half++) {
            int gr = m0 + lr_base + tm * 16 + half * 8;
            if (gr < Ne) {
                if (PHASE == 1) {
                    size_t pr = (size_t)(base + gr);
#pragma unroll
                    for (int tn = 0; tn < 8; tn++) {
                        int col = col_base + tn * 8;
                        float c0 = fmaxf(acc[tm][tn][half * 2 + 0] + __ldg(bp + col),     0.f);
                        float c1 = fmaxf(acc[tm][tn][half * 2 + 1] + __ldg(bp + col + 1), 0.f);
                        __half2 hp;
                        hp.x = __float2half_rn(c0);
                        hp.y = __float2half_rn(c1);
                        *(__half2*)(g_hh + pr * H_DIM + col) = hp;
                    }
                } else {
                    int   tok = g_tok[e * CAP + gr];
                    float w   = g_wt [e * CAP + gr];
                    float* op = out + (size_t)tok * NDIM;
#pragma unroll
                    for (int tn = 0; tn < 8; tn++) {
                        int col = col_base + tn * 8;
                        float v0 = w * (acc[tm][tn][half * 2 + 0] + __ldg(bp + col));
                        float v1 = w * (acc[tm][tn][half * 2 + 1] + __ldg(bp + col + 1));
                        red_add_v2(op + col, v0, v1);
                    }
                }
            }
        }
    }
}

// ---------------- launch ----------------
extern "C" void kernel_launch(void* const* d_in, const int* in_sizes, int n_in,
                              void* d_out, int out_size) {
    const float* x  = (const float*)d_in[0];
    const float* Wr = (const float*)d_in[1];
    const float* br = (const float*)d_in[2];
    const float* W1 = (const float*)d_in[3];
    const float* b1 = (const float*)d_in[4];
    const float* W2 = (const float*)d_in[5];
    const float* b2 = (const float*)d_in[6];
    float* out = (float*)d_out;

    const int SMEM1 = 4 * (128 + 256) * ROWB;   // 122880
    const int SMEM2 = 4 * (128 + 256) * ROWB;   // 122880

    cudaFuncSetAttribute(moe_hmma<1, D_DIM, H_DIM, 4>,
                         cudaFuncAttributeMaxDynamicSharedMemorySize, SMEM1);
    cudaFuncSetAttribute(moe_hmma<2, H_DIM, D_DIM, 4>,
                         cudaFuncAttributeMaxDynamicSharedMemorySize, SMEM2);

    __half *xh, *hh, *B1h, *B2h;
    cudaGetSymbolAddress((void**)&xh,  g_xh);
    cudaGetSymbolAddress((void**)&hh,  g_hh);
    cudaGetSymbolAddress((void**)&B1h, g_B1h); cudaGetSymbolAddress((void**)&B2h, g_B2h);

    zero_kernel<<<1024, 256>>>(out, out_size);
    {   // W1: K=1024, N=4096 -> [E][4096][1024]
        dim3 g(D_DIM / 32, H_DIM / 32, E_NUM);
        pack_w_kernel<<<g, 256>>>(W1, B1h, D_DIM, H_DIM);
    }
    {   // W2: K=4096, N=1024 -> [E][1024][4096]
        dim3 g(H_DIM / 32, D_DIM / 32, E_NUM);
        pack_w_kernel<<<g, 256>>>(W2, B2h, H_DIM, D_DIM);
    }
    router_kernel<<<(N_TOK * 32 + 255) / 256, 256>>>(x, Wr, br);
    offsets_kernel<<<1, 32>>>();

    {   // GEMM1: gathered x [Ne,1024] @ W1 -> relu -> h (fp16); TM=128, 512 thr
        dim3 g(CAP / 128, H_DIM / 256, E_NUM);
        moe_hmma<1, D_DIM, H_DIM, 4><<<g, 512, SMEM1>>>(xh, B1h, b1, nullptr);
    }
    {   // GEMM2: h [Ne,4096] @ W2 -> weighted red.v2 scatter; TM=128, 512 thr
        dim3 g(CAP / 128, D_DIM / 256, E_NUM);
        moe_hmma<2, H_DIM, D_DIM, 4><<<g, 512, SMEM2>>>(hh, B2h, b2, out);
    }
}